// round 1
// baseline (speedup 1.0000x reference)
#include <cuda_runtime.h>

// Problem dims
constexpr int CD    = 512;
constexpr int NB    = 16;
constexpr int NN    = 64;
constexpr int XROWS = NB * NN;        // 1024
constexpr int XEL   = XROWS * CD;     // 524288
constexpr int EROWS = NB * NN * NN;   // 65536

// Scratch (no allocation allowed -> __device__ globals)
__device__ float g_Vix[XEL];
__device__ float g_Vjx[XEL];
__device__ float g_Ujx[XEL];
__device__ float g_xWU[XEL];
__device__ float g_agg[XEL];
__device__ float g_x1 [XEL];

constexpr int WS_LD       = 513;                       // padded to kill STS bank conflicts
constexpr int SMEM_FLOATS = 32 * CD + 16 * WS_LD;      // 24592 floats = 98368 B

__device__ __forceinline__ float warp_sum(float v) {
#pragma unroll
    for (int o = 16; o > 0; o >>= 1) v += __shfl_xor_sync(0xffffffffu, v, o);
    return v;
}

// Accumulate 32x512 output tile: acc[u][v] += sum_k Es[row][k] * W[c][k]
// thread layout: tj = warp (0..7) owns rows {tj, tj+8, tj+16, tj+24}; tc = lane owns c = tc + 32*v
__device__ __forceinline__ void gemm_accum(const float* __restrict__ W,
                                           const float* Es, float* Ws,
                                           int tid, int tj, int tc,
                                           float acc[4][16]) {
    for (int k0 = 0; k0 < CD; k0 += 16) {
        __syncthreads();   // prev-iter compute done (also guards initial Es fill)
#pragma unroll
        for (int q = 0; q < 32; q++) {           // load W[c][k0..k0+15] transposed
            int t  = tid + q * 256;
            int c  = t >> 4;
            int kk = t & 15;
            Ws[kk * WS_LD + c] = W[c * CD + k0 + kk];
        }
        __syncthreads();
#pragma unroll
        for (int kk = 0; kk < 16; kk++) {
            float e0 = Es[(tj +  0) * CD + k0 + kk];   // broadcast LDS
            float e1 = Es[(tj +  8) * CD + k0 + kk];
            float e2 = Es[(tj + 16) * CD + k0 + kk];
            float e3 = Es[(tj + 24) * CD + k0 + kk];
            const float* wrow = &Ws[kk * WS_LD + tc];
#pragma unroll
            for (int v = 0; v < 16; v++) {
                float w = wrow[32 * v];                // conflict-free LDS
                acc[0][v] = fmaf(e0, w, acc[0][v]);
                acc[1][v] = fmaf(e1, w, acc[1][v]);
                acc[2][v] = fmaf(e2, w, acc[2][v]);
                acc[3][v] = fmaf(e3, w, acc[3][v]);
            }
        }
    }
}

// ---------------------------------------------------------------------------
// Kernel 1: 4 batched x-GEMMs  (Vix = x@WA.T, Vjx = x@WB.T, Ujx = x@WV.T, xWU = x@WU.T)
// grid (32, 4), 256 thr
// ---------------------------------------------------------------------------
extern "C" __global__ void __launch_bounds__(256, 2)
gemm4_kernel(const float* __restrict__ X,
             const float* __restrict__ WA, const float* __restrict__ WB,
             const float* __restrict__ WV, const float* __restrict__ WU) {
    extern __shared__ float sm[];
    float* Es = sm;
    float* Ws = sm + 32 * CD;
    int tid = threadIdx.x, tc = tid & 31, tj = tid >> 5;
    int rowBase = blockIdx.x * 32;

    const float* W = (blockIdx.y == 0) ? WA : (blockIdx.y == 1) ? WB
                   : (blockIdx.y == 2) ? WV : WU;
    float* O = (blockIdx.y == 0) ? g_Vix : (blockIdx.y == 1) ? g_Vjx
             : (blockIdx.y == 2) ? g_Ujx : g_xWU;

    const float4* src  = (const float4*)(X + (size_t)rowBase * CD);
    float4*       dst4 = (float4*)Es;
#pragma unroll
    for (int q = 0; q < 16; q++) dst4[tid + q * 256] = src[tid + q * 256];

    float acc[4][16];
#pragma unroll
    for (int u = 0; u < 4; u++)
#pragma unroll
        for (int v = 0; v < 16; v++) acc[u][v] = 0.f;

    gemm_accum(W, Es, Ws, tid, tj, tc, acc);

#pragma unroll
    for (int u = 0; u < 4; u++) {
        float* op = O + (size_t)(rowBase + tj + 8 * u) * CD + tc;
#pragma unroll
        for (int v = 0; v < 16; v++) op[32 * v] = acc[u][v];
    }
}

// ---------------------------------------------------------------------------
// Kernel 2: fused  edge_out = edge + relu(LN(edge@WE.T + Vix[b,i] + Vjx[b,j]))
// one CTA per 32 consecutive edge rows (all sharing (b,i)); safe in-place.
// grid 2048, 256 thr
// ---------------------------------------------------------------------------
extern "C" __global__ void __launch_bounds__(256, 2)
edge_fused_kernel(const float* __restrict__ Ein, const float* __restrict__ WE,
                  const float* __restrict__ ge,  const float* __restrict__ be,
                  float* __restrict__ Eout) {
    extern __shared__ float sm[];
    float* Es = sm;
    float* Ws = sm + 32 * CD;
    int tid = threadIdx.x, tc = tid & 31, tj = tid >> 5;
    int rowBase = blockIdx.x * 32;
    int b  = rowBase >> 12;        // /4096
    int i  = (rowBase >> 6) & 63;
    int j0 = rowBase & 63;         // 0 or 32

    const float4* src  = (const float4*)(Ein + (size_t)rowBase * CD);
    float4*       dst4 = (float4*)Es;
#pragma unroll
    for (int q = 0; q < 16; q++) dst4[tid + q * 256] = src[tid + q * 256];

    float acc[4][16];
#pragma unroll
    for (int u = 0; u < 4; u++)
#pragma unroll
        for (int v = 0; v < 16; v++) acc[u][v] = 0.f;

    gemm_accum(WE, Es, Ws, tid, tj, tc, acc);

    float vix[16], g[16], bb[16];
#pragma unroll
    for (int v = 0; v < 16; v++) {
        int c  = tc + 32 * v;
        vix[v] = g_Vix[(size_t)(b * NN + i) * CD + c];
        g[v]   = ge[c];
        bb[v]  = be[c];
    }
#pragma unroll
    for (int u = 0; u < 4; u++) {
        int jl   = tj + 8 * u;                       // local row 0..31
        int grow = rowBase + jl;                     // global edge row
        const float* vj = &g_Vjx[(size_t)(b * NN + j0 + jl) * CD + tc];
        float m[16];
        float s = 0.f;
#pragma unroll
        for (int v = 0; v < 16; v++) {
            m[v] = acc[u][v] + vix[v] + vj[32 * v];
            s += m[v];
        }
        s = warp_sum(s);
        float mean = s * (1.f / CD);
        float q = 0.f;
#pragma unroll
        for (int v = 0; v < 16; v++) { float d = m[v] - mean; q += d * d; }
        q = warp_sum(q);
        float inv = rsqrtf(q * (1.f / CD) + 1e-5f);
        float* outp = Eout + (size_t)grow * CD + tc;
#pragma unroll
        for (int v = 0; v < 16; v++) {
            float val = (m[v] - mean) * inv * g[v] + bb[v];
            val = fmaxf(val, 0.f);
            outp[32 * v] = Es[jl * CD + tc + 32 * v] + val;
        }
    }
}

// ---------------------------------------------------------------------------
// Kernel 3: one-pass softmax-over-j of sigmoid(edge) + weighted agg with Ujx
// agg[b,i,c] = (sum_j e*Ujx) / (sum_j e) / 64   where e = exp(sigmoid(edge))
// grid 1024 (=b*64+i), 512 thr (one c per thread)
// ---------------------------------------------------------------------------
extern "C" __global__ void softmax_agg_kernel(const float* __restrict__ E) {
    int bi = blockIdx.x;
    int b  = bi >> 6;
    int c  = threadIdx.x;
    const float* ep = E     + (size_t)bi * NN * CD + c;
    const float* up = g_Ujx + (size_t)b  * NN * CD + c;
    float se = 0.f, sw = 0.f;
#pragma unroll 4
    for (int j = 0; j < NN; j++) {
        float v  = ep[(size_t)j * CD];
        float sg = 1.f / (1.f + __expf(-v));
        float e  = __expf(sg);                 // sigmoid in (0,1): no max-sub needed
        se += e;
        sw = fmaf(e, up[(size_t)j * CD], sw);
    }
    g_agg[(size_t)bi * CD + c] = sw / (se * (float)NN);
}

// ---------------------------------------------------------------------------
// Kernel 4: x_out = relu(x_res + LN(xWU + agg))   — one warp per row
// grid 128, 256 thr
// ---------------------------------------------------------------------------
extern "C" __global__ void x_update_kernel(const float* __restrict__ xres,
                                           const float* __restrict__ gv,
                                           const float* __restrict__ bv,
                                           float* __restrict__ xout) {
    int warp = threadIdx.x >> 5, lane = threadIdx.x & 31;
    int row  = blockIdx.x * 8 + warp;
    const float* a  = g_xWU + (size_t)row * CD;
    const float* ag = g_agg + (size_t)row * CD;
    float t[16];
    float s = 0.f;
#pragma unroll
    for (int v = 0; v < 16; v++) {
        int c = lane + 32 * v;
        t[v]  = a[c] + ag[c];
        s += t[v];
    }
    s = warp_sum(s);
    float mean = s * (1.f / CD);
    float q = 0.f;
#pragma unroll
    for (int v = 0; v < 16; v++) { float d = t[v] - mean; q += d * d; }
    q = warp_sum(q);
    float inv = rsqrtf(q * (1.f / CD) + 1e-5f);
    const float* r = xres + (size_t)row * CD;
    float*       o = xout + (size_t)row * CD;
#pragma unroll
    for (int v = 0; v < 16; v++) {
        int c = lane + 32 * v;
        float val = (t[v] - mean) * inv * gv[c] + bv[c];
        o[c] = fmaxf(r[c] + val, 0.f);
    }
}

// ---------------------------------------------------------------------------
extern "C" void kernel_launch(void* const* d_in, const int* in_sizes, int n_in,
                              void* d_out, int out_size) {
    const float* x    = (const float*)d_in[0];
    const float* edge = (const float*)d_in[1];
    const float* WA1  = (const float*)d_in[2];
    const float* WB1  = (const float*)d_in[3];
    const float* WE1  = (const float*)d_in[4];
    const float* WU1  = (const float*)d_in[5];
    const float* WV1  = (const float*)d_in[6];
    const float* WA2  = (const float*)d_in[7];
    const float* WB2  = (const float*)d_in[8];
    const float* WE2  = (const float*)d_in[9];
    const float* WU2  = (const float*)d_in[10];
    const float* WV2  = (const float*)d_in[11];
    // setup_inputs() dict order: gammas first (ge1, gv1, ge2, gv2), then betas
    const float* ge1  = (const float*)d_in[12];
    const float* gv1  = (const float*)d_in[13];
    const float* ge2  = (const float*)d_in[14];
    const float* gv2  = (const float*)d_in[15];
    const float* be1  = (const float*)d_in[16];
    const float* bv1  = (const float*)d_in[17];
    const float* be2  = (const float*)d_in[18];
    const float* bv2  = (const float*)d_in[19];

    float* xout = (float*)d_out;          // [1024, 512]
    float* eout = (float*)d_out + XEL;    // [65536, 512]

    void* p = nullptr;
    cudaGetSymbolAddress(&p, g_x1);
    float* x1 = (float*)p;

    const size_t smem = SMEM_FLOATS * sizeof(float);
    cudaFuncSetAttribute(gemm4_kernel,      cudaFuncAttributeMaxDynamicSharedMemorySize, (int)smem);
    cudaFuncSetAttribute(edge_fused_kernel, cudaFuncAttributeMaxDynamicSharedMemorySize, (int)smem);

    // ---- layer 1 ----
    gemm4_kernel<<<dim3(32, 4), 256, smem>>>(x, WA1, WB1, WV1, WU1);
    edge_fused_kernel<<<EROWS / 32, 256, smem>>>(edge, WE1, ge1, be1, eout);
    softmax_agg_kernel<<<XROWS, 512>>>(eout);
    x_update_kernel<<<XROWS / 8, 256>>>(x, gv1, bv1, x1);

    // ---- layer 2 (edge path in place on eout) ----
    gemm4_kernel<<<dim3(32, 4), 256, smem>>>(x1, WA2, WB2, WV2, WU2);
    edge_fused_kernel<<<EROWS / 32, 256, smem>>>(eout, WE2, ge2, be2, eout);
    softmax_agg_kernel<<<XROWS, 512>>>(eout);
    x_update_kernel<<<XROWS / 8, 256>>>(x1, gv2, bv2, xout);
}

// round 5
// speedup vs baseline: 2.4297x; 2.4297x over previous
#include <cuda_runtime.h>
#include <cuda_bf16.h>
#include <cstdint>

// Problem dims
constexpr int CD    = 512;
constexpr int NB    = 16;
constexpr int NN    = 64;
constexpr int XROWS = NB * NN;        // 1024
constexpr int XEL   = XROWS * CD;     // 524288
constexpr int EROWS = NB * NN * NN;   // 65536

// Scratch (no allocation allowed -> __device__ globals)
__device__ float g_Vix[XEL];
__device__ float g_Vjx[XEL];
__device__ float g_Ujx[XEL];
__device__ float g_xWU[XEL];
__device__ float g_agg[XEL];
__device__ float g_x1 [XEL];
__device__ float g_m  [EROWS * CD];                 // 134 MB pre-LN scratch
__device__ __nv_bfloat16 g_wehi[2 * CD * CD];        // WE1, WE2 hi
__device__ __nv_bfloat16 g_welo[2 * CD * CD];
__device__ __nv_bfloat16 g_wxhi[2 * 4 * CD * CD];    // per layer: WA,WB,WV,WU
__device__ __nv_bfloat16 g_wxlo[2 * 4 * CD * CD];

// ======================= helpers =======================
__device__ __forceinline__ uint32_t smem_u32(const void* p) {
    uint32_t a;
    asm("{ .reg .u64 t; cvta.to.shared.u64 t, %1; cvt.u32.u64 %0, t; }" : "=r"(a) : "l"(p));
    return a;
}
__device__ __forceinline__ void ldm_x4(uint32_t addr, uint32_t& r0, uint32_t& r1,
                                       uint32_t& r2, uint32_t& r3) {
    asm volatile("ldmatrix.sync.aligned.m8n8.x4.shared.b16 {%0,%1,%2,%3}, [%4];"
                 : "=r"(r0), "=r"(r1), "=r"(r2), "=r"(r3) : "r"(addr));
}
__device__ __forceinline__ void mma_bf16(float* c, uint32_t a0, uint32_t a1, uint32_t a2,
                                         uint32_t a3, uint32_t b0, uint32_t b1) {
    asm volatile(
        "mma.sync.aligned.m16n8k16.row.col.f32.bf16.bf16.f32 "
        "{%0,%1,%2,%3}, {%4,%5,%6,%7}, {%8,%9}, {%0,%1,%2,%3};"
        : "+f"(c[0]), "+f"(c[1]), "+f"(c[2]), "+f"(c[3])
        : "r"(a0), "r"(a1), "r"(a2), "r"(a3), "r"(b0), "r"(b1));
}
__device__ __forceinline__ void sts64(uint32_t addr, uint32_t w0, uint32_t w1) {
    asm volatile("st.shared.v2.b32 [%0], {%1, %2};" :: "r"(addr), "r"(w0), "r"(w1) : "memory");
}
__device__ __forceinline__ void sts128(uint32_t addr, uint4 v) {
    asm volatile("st.shared.v4.b32 [%0], {%1, %2, %3, %4};"
                 :: "r"(addr), "r"(v.x), "r"(v.y), "r"(v.z), "r"(v.w) : "memory");
}
__device__ __forceinline__ uint32_t pack_bf16(float a, float b) {
    __nv_bfloat162 t = __floats2bfloat162_rn(a, b);
    return *reinterpret_cast<uint32_t*>(&t);
}
__device__ __forceinline__ float warp_sum(float v) {
#pragma unroll
    for (int o = 16; o > 0; o >>= 1) v += __shfl_xor_sync(0xffffffffu, v, o);
    return v;
}

// ======================= kernel 0: weight split =======================
extern "C" __global__ void wsplit_kernel(const float* __restrict__ src,
                                         __nv_bfloat16* __restrict__ hi,
                                         __nv_bfloat16* __restrict__ lo) {
    int idx = blockIdx.x * 256 + threadIdx.x;
    float v = src[idx];
    __nv_bfloat16 h = __float2bfloat16(v);
    hi[idx] = h;
    lo[idx] = __float2bfloat16(v - __bfloat162float(h));
}

// ======================= MMA GEMM (bf16 3-split) =======================
// CTA tile: 128 rows x 128 cols; 8 warps (wm 0..3 x wn 0..1), warp tile 32x64.
// K chunk: 32 fp32. A split on the fly to hi/lo bf16; B pre-split (hi/lo).
// MODE 0: x-GEMM   (A = x [1024x512], B = 4 concatenated weights, N = 2048;
//                   output routed to g_Vix/g_Vjx/g_Ujx/g_xWU by column block)
// MODE 1: edge GEMM (A = edge [65536x512], B = WE; writes g_m += Vix + Vjx)
constexpr int KC  = 32;
constexpr int AST = 40;   // smem row stride (bf16 elems) = 80 B; kills ldmatrix conflicts

template <int MODE>
__global__ void __launch_bounds__(256, 2)
mma_gemm_kernel(const float* __restrict__ A,
                const __nv_bfloat16* __restrict__ Bhi,
                const __nv_bfloat16* __restrict__ Blo) {
    __shared__ __nv_bfloat16 s_ahi[128 * AST];
    __shared__ __nv_bfloat16 s_alo[128 * AST];
    __shared__ __nv_bfloat16 s_bhi[128 * AST];
    __shared__ __nv_bfloat16 s_blo[128 * AST];

    int tid = threadIdx.x, lane = tid & 31, wid = tid >> 5;
    int rowBase = blockIdx.x * 128;
    int colBase = blockIdx.y * 128;
    int wm = wid & 3, wn = wid >> 2;

    uint32_t ua_hi = smem_u32(s_ahi), ua_lo = smem_u32(s_alo);
    uint32_t ub_hi = smem_u32(s_bhi), ub_lo = smem_u32(s_blo);

    float acc[2][8][4];
#pragma unroll
    for (int mt = 0; mt < 2; mt++)
#pragma unroll
        for (int nt = 0; nt < 8; nt++)
#pragma unroll
            for (int q = 0; q < 4; q++) acc[mt][nt][q] = 0.f;

    int rr = tid >> 1, half = tid & 1;
    const float*         aptr = A   + (size_t)(rowBase + rr) * CD + half * 16;
    const __nv_bfloat16* bh   = Bhi + (size_t)(colBase + rr) * CD + half * 16;
    const __nv_bfloat16* bl   = Blo + (size_t)(colBase + rr) * CD + half * 16;
    uint32_t soff = (uint32_t)(rr * AST + half * 16) * 2;   // byte offset in smem

    for (int k0 = 0; k0 < CD; k0 += KC) {
        __syncthreads();
        // ---- A chunk: fp32 -> bf16 hi/lo ----
#pragma unroll
        for (int q = 0; q < 4; q++) {
            float4 v = *(const float4*)(aptr + k0 + q * 4);
            float hx = __bfloat162float(__float2bfloat16(v.x));
            float hy = __bfloat162float(__float2bfloat16(v.y));
            float hz = __bfloat162float(__float2bfloat16(v.z));
            float hw = __bfloat162float(__float2bfloat16(v.w));
            sts64(ua_hi + soff + q * 8, pack_bf16(hx, hy), pack_bf16(hz, hw));
            sts64(ua_lo + soff + q * 8,
                  pack_bf16(v.x - hx, v.y - hy), pack_bf16(v.z - hz, v.w - hw));
        }
        // ---- B chunk: pre-split bf16 copy ----
#pragma unroll
        for (int q = 0; q < 2; q++) {
            sts128(ub_hi + soff + q * 16, *(const uint4*)(bh + k0 + q * 8));
            sts128(ub_lo + soff + q * 16, *(const uint4*)(bl + k0 + q * 8));
        }
        __syncthreads();

#pragma unroll
        for (int seg = 0; seg < 3; seg++) {
            uint32_t sa = (seg == 1) ? ua_lo : ua_hi;
            uint32_t sb = (seg == 2) ? ub_lo : ub_hi;
#pragma unroll
            for (int kk = 0; kk < 2; kk++) {
                uint32_t a[2][4];
#pragma unroll
                for (int mt = 0; mt < 2; mt++) {
                    int row = wm * 32 + mt * 16 + (lane & 15);
                    int kel = kk * 16 + ((lane >> 4) << 3);
                    ldm_x4(sa + (uint32_t)(row * AST + kel) * 2,
                           a[mt][0], a[mt][1], a[mt][2], a[mt][3]);
                }
                uint32_t b[8][2];
#pragma unroll
                for (int np = 0; np < 4; np++) {
                    int n   = wn * 64 + np * 16 + (lane & 7) + ((lane >> 4) << 3);
                    int kel = kk * 16 + (((lane >> 3) & 1) << 3);
                    uint32_t r0, r1, r2, r3;
                    ldm_x4(sb + (uint32_t)(n * AST + kel) * 2, r0, r1, r2, r3);
                    b[np * 2][0] = r0; b[np * 2][1] = r1;
                    b[np * 2 + 1][0] = r2; b[np * 2 + 1][1] = r3;
                }
#pragma unroll
                for (int mt = 0; mt < 2; mt++)
#pragma unroll
                    for (int nt = 0; nt < 8; nt++)
                        mma_bf16(acc[mt][nt], a[mt][0], a[mt][1], a[mt][2], a[mt][3],
                                 b[nt][0], b[nt][1]);
            }
        }
    }

    // ---- epilogue ----
    int r0 = wm * 32 + (lane >> 2);
    int c0 = wn * 64 + (lane & 3) * 2;

    if (MODE == 0) {
        const int mat = colBase >> 9;
        float* O = (mat == 0) ? g_Vix : (mat == 1) ? g_Vjx : (mat == 2) ? g_Ujx : g_xWU;
        int cb = colBase & 511;
#pragma unroll
        for (int mt = 0; mt < 2; mt++) {
            int gr = rowBase + r0 + mt * 16;
#pragma unroll
            for (int nt = 0; nt < 8; nt++) {
                int c = cb + c0 + nt * 8;
                *(float2*)&O[(size_t)gr * CD + c] =
                    make_float2(acc[mt][nt][0], acc[mt][nt][1]);
                *(float2*)&O[(size_t)(gr + 8) * CD + c] =
                    make_float2(acc[mt][nt][2], acc[mt][nt][3]);
            }
        }
    } else {
#pragma unroll
        for (int mt = 0; mt < 2; mt++) {
#pragma unroll
            for (int hh = 0; hh < 2; hh++) {
                int gr = rowBase + r0 + mt * 16 + hh * 8;
                int bI = gr >> 12, iI = (gr >> 6) & 63, jI = gr & 63;
                const float* vix = g_Vix + (size_t)((bI << 6) + iI) * CD;
                const float* vjx = g_Vjx + (size_t)((bI << 6) + jI) * CD;
#pragma unroll
                for (int nt = 0; nt < 8; nt++) {
                    int c = colBase + c0 + nt * 8;
                    float2 vi = *(const float2*)&vix[c];
                    float2 vj = *(const float2*)&vjx[c];
                    float2 o;
                    o.x = acc[mt][nt][hh * 2 + 0] + vi.x + vj.x;
                    o.y = acc[mt][nt][hh * 2 + 1] + vi.y + vj.y;
                    *(float2*)&g_m[(size_t)gr * CD + c] = o;
                }
            }
        }
    }
}

// ======================= LN over edge rows =======================
// eout = ein + relu(LN(g_m))  ; one warp per edge row
extern "C" __global__ void ln_edge_kernel(const float* __restrict__ Ein,
                                          const float* __restrict__ ge,
                                          const float* __restrict__ be,
                                          float* __restrict__ Eout) {
    int wid = threadIdx.x >> 5, lane = threadIdx.x & 31;
    size_t row = (size_t)blockIdx.x * 8 + wid;
    const float* mrow = g_m + row * CD;
    float t[16];
    float s = 0.f;
#pragma unroll
    for (int v = 0; v < 16; v++) { t[v] = mrow[lane + 32 * v]; s += t[v]; }
    s = warp_sum(s);
    float mean = s * (1.f / CD);
    float q = 0.f;
#pragma unroll
    for (int v = 0; v < 16; v++) { float d = t[v] - mean; q += d * d; }
    q = warp_sum(q);
    float inv = rsqrtf(q * (1.f / CD) + 1e-5f);
    const float* ein = Ein + row * CD;
    float*       eo  = Eout + row * CD;
#pragma unroll
    for (int v = 0; v < 16; v++) {
        int c = lane + 32 * v;
        float val = (t[v] - mean) * inv * ge[c] + be[c];
        eo[c] = ein[c] + fmaxf(val, 0.f);
    }
}

// ======================= softmax-over-j + weighted agg =======================
extern "C" __global__ void softmax_agg_kernel(const float* __restrict__ E) {
    int bi = blockIdx.x;
    int b  = bi >> 6;
    int c  = threadIdx.x;
    const float* ep = E     + (size_t)bi * NN * CD + c;
    const float* up = g_Ujx + (size_t)b  * NN * CD + c;
    float se = 0.f, sw = 0.f;
#pragma unroll 4
    for (int j = 0; j < NN; j++) {
        float v  = ep[(size_t)j * CD];
        float sg = 1.f / (1.f + __expf(-v));
        float e  = __expf(sg);
        se += e;
        sw = fmaf(e, up[(size_t)j * CD], sw);
    }
    g_agg[(size_t)bi * CD + c] = sw / (se * (float)NN);
}

// ======================= x update =======================
extern "C" __global__ void x_update_kernel(const float* __restrict__ xres,
                                           const float* __restrict__ gv,
                                           const float* __restrict__ bv,
                                           float* __restrict__ xout) {
    int warp = threadIdx.x >> 5, lane = threadIdx.x & 31;
    int row  = blockIdx.x * 8 + warp;
    const float* a  = g_xWU + (size_t)row * CD;
    const float* ag = g_agg + (size_t)row * CD;
    float t[16];
    float s = 0.f;
#pragma unroll
    for (int v = 0; v < 16; v++) {
        int c = lane + 32 * v;
        t[v]  = a[c] + ag[c];
        s += t[v];
    }
    s = warp_sum(s);
    float mean = s * (1.f / CD);
    float q = 0.f;
#pragma unroll
    for (int v = 0; v < 16; v++) { float d = t[v] - mean; q += d * d; }
    q = warp_sum(q);
    float inv = rsqrtf(q * (1.f / CD) + 1e-5f);
    const float* r = xres + (size_t)row * CD;
    float*       o = xout + (size_t)row * CD;
#pragma unroll
    for (int v = 0; v < 16; v++) {
        int c = lane + 32 * v;
        float val = (t[v] - mean) * inv * gv[c] + bv[c];
        o[c] = fmaxf(r[c] + val, 0.f);
    }
}

// ===========================================================================
extern "C" void kernel_launch(void* const* d_in, const int* in_sizes, int n_in,
                              void* d_out, int out_size) {
    const float* x    = (const float*)d_in[0];
    const float* edge = (const float*)d_in[1];
    const float* WA1  = (const float*)d_in[2];
    const float* WB1  = (const float*)d_in[3];
    const float* WE1  = (const float*)d_in[4];
    const float* WU1  = (const float*)d_in[5];
    const float* WV1  = (const float*)d_in[6];
    const float* WA2  = (const float*)d_in[7];
    const float* WB2  = (const float*)d_in[8];
    const float* WE2  = (const float*)d_in[9];
    const float* WU2  = (const float*)d_in[10];
    const float* WV2  = (const float*)d_in[11];
    const float* ge1  = (const float*)d_in[12];
    const float* gv1  = (const float*)d_in[13];
    const float* ge2  = (const float*)d_in[14];
    const float* gv2  = (const float*)d_in[15];
    const float* be1  = (const float*)d_in[16];
    const float* bv1  = (const float*)d_in[17];
    const float* be2  = (const float*)d_in[18];
    const float* bv2  = (const float*)d_in[19];

    float* xout = (float*)d_out;
    float* eout = (float*)d_out + XEL;

    void* p = nullptr;
    cudaGetSymbolAddress(&p, g_x1);   float* x1 = (float*)p;
    cudaGetSymbolAddress(&p, g_wehi); __nv_bfloat16* wehi = (__nv_bfloat16*)p;
    cudaGetSymbolAddress(&p, g_welo); __nv_bfloat16* welo = (__nv_bfloat16*)p;
    cudaGetSymbolAddress(&p, g_wxhi); __nv_bfloat16* wxhi = (__nv_bfloat16*)p;
    cudaGetSymbolAddress(&p, g_wxlo); __nv_bfloat16* wxlo = (__nv_bfloat16*)p;

    const int WSZ = CD * CD;  // 262144
    // weight split: WE per layer; x-weights packed [WA, WB, WV, WU] per layer
    wsplit_kernel<<<WSZ / 256, 256>>>(WE1, wehi,                 welo);
    wsplit_kernel<<<WSZ / 256, 256>>>(WE2, wehi + WSZ,           welo + WSZ);
    wsplit_kernel<<<WSZ / 256, 256>>>(WA1, wxhi,                 wxlo);
    wsplit_kernel<<<WSZ / 256, 256>>>(WB1, wxhi + WSZ,           wxlo + WSZ);
    wsplit_kernel<<<WSZ / 256, 256>>>(WV1, wxhi + 2 * WSZ,       wxlo + 2 * WSZ);
    wsplit_kernel<<<WSZ / 256, 256>>>(WU1, wxhi + 3 * WSZ,       wxlo + 3 * WSZ);
    wsplit_kernel<<<WSZ / 256, 256>>>(WA2, wxhi + 4 * WSZ,       wxlo + 4 * WSZ);
    wsplit_kernel<<<WSZ / 256, 256>>>(WB2, wxhi + 5 * WSZ,       wxlo + 5 * WSZ);
    wsplit_kernel<<<WSZ / 256, 256>>>(WV2, wxhi + 6 * WSZ,       wxlo + 6 * WSZ);
    wsplit_kernel<<<WSZ / 256, 256>>>(WU2, wxhi + 7 * WSZ,       wxlo + 7 * WSZ);

    // ---- layer 1 ----
    mma_gemm_kernel<0><<<dim3(XROWS / 128, 16), 256>>>(x, wxhi, wxlo);
    mma_gemm_kernel<1><<<dim3(EROWS / 128, 4), 256>>>(edge, wehi, welo);
    ln_edge_kernel<<<EROWS / 8, 256>>>(edge, ge1, be1, eout);
    softmax_agg_kernel<<<XROWS, 512>>>(eout);
    x_update_kernel<<<XROWS / 8, 256>>>(x, gv1, bv1, x1);

    // ---- layer 2 (edge path in place on eout) ----
    mma_gemm_kernel<0><<<dim3(XROWS / 128, 16), 256>>>(x1, wxhi + 4 * WSZ, wxlo + 4 * WSZ);
    mma_gemm_kernel<1><<<dim3(EROWS / 128, 4), 256>>>(eout, wehi + WSZ, welo + WSZ);
    ln_edge_kernel<<<EROWS / 8, 256>>>(eout, ge2, be2, eout);
    softmax_agg_kernel<<<XROWS, 512>>>(eout);
    x_update_kernel<<<XROWS / 8, 256>>>(x1, gv2, bv2, xout);
}

// round 8
// speedup vs baseline: 3.4612x; 1.4245x over previous
#include <cuda_runtime.h>
#include <cuda_fp16.h>
#include <cstdint>

// Problem dims
constexpr int CD    = 512;
constexpr int NB    = 16;
constexpr int NN    = 64;
constexpr int XROWS = NB * NN;        // 1024
constexpr int XEL   = XROWS * CD;     // 524288
constexpr int EROWS = NB * NN * NN;   // 65536
constexpr int WSZ   = CD * CD;        // 262144

// Scratch (no allocation allowed -> __device__ globals)
__device__ float g_Vix[XEL];
__device__ float g_Vjx[XEL];
__device__ float g_Ujx[XEL];
__device__ float g_xWU[XEL];
__device__ float g_agg[XEL];
__device__ float g_x1 [XEL];
// fp16 weights: [0]=WE1 [1]=WE2 [2..5]=WA1,WB1,WV1,WU1 [6..9]=WA2,WB2,WV2,WU2
__device__ __half g_wh[10 * WSZ];

// ======================= helpers =======================
__device__ __forceinline__ uint32_t smem_u32(const void* p) {
    uint32_t a;
    asm("{ .reg .u64 t; cvta.to.shared.u64 t, %1; cvt.u32.u64 %0, t; }" : "=r"(a) : "l"(p));
    return a;
}
__device__ __forceinline__ void ldm_x4(uint32_t addr, uint32_t& r0, uint32_t& r1,
                                       uint32_t& r2, uint32_t& r3) {
    asm volatile("ldmatrix.sync.aligned.m8n8.x4.shared.b16 {%0,%1,%2,%3}, [%4];"
                 : "=r"(r0), "=r"(r1), "=r"(r2), "=r"(r3) : "r"(addr));
}
__device__ __forceinline__ void mma_f16(float* c, uint32_t a0, uint32_t a1, uint32_t a2,
                                        uint32_t a3, uint32_t b0, uint32_t b1) {
    asm volatile(
        "mma.sync.aligned.m16n8k16.row.col.f32.f16.f16.f32 "
        "{%0,%1,%2,%3}, {%4,%5,%6,%7}, {%8,%9}, {%0,%1,%2,%3};"
        : "+f"(c[0]), "+f"(c[1]), "+f"(c[2]), "+f"(c[3])
        : "r"(a0), "r"(a1), "r"(a2), "r"(a3), "r"(b0), "r"(b1));
}
__device__ __forceinline__ void sts64(uint32_t addr, uint32_t w0, uint32_t w1) {
    asm volatile("st.shared.v2.b32 [%0], {%1, %2};" :: "r"(addr), "r"(w0), "r"(w1) : "memory");
}
__device__ __forceinline__ void sts128(uint32_t addr, uint4 v) {
    asm volatile("st.shared.v4.b32 [%0], {%1, %2, %3, %4};"
                 :: "r"(addr), "r"(v.x), "r"(v.y), "r"(v.z), "r"(v.w) : "memory");
}
__device__ __forceinline__ void cp_async16(uint32_t smem, const void* g) {
    asm volatile("cp.async.cg.shared.global [%0], [%1], 16;" :: "r"(smem), "l"(g) : "memory");
}
#define CP_COMMIT()  asm volatile("cp.async.commit_group;" ::: "memory")
#define CP_WAIT_1()  asm volatile("cp.async.wait_group 1;" ::: "memory")
#define CP_WAIT_0()  asm volatile("cp.async.wait_group 0;" ::: "memory")

__device__ __forceinline__ uint32_t pack_h2(__half a, __half b) {
    __half2 t = __halves2half2(a, b);
    return *reinterpret_cast<uint32_t*>(&t);
}
__device__ __forceinline__ float warp_sum(float v) {
#pragma unroll
    for (int o = 16; o > 0; o >>= 1) v += __shfl_xor_sync(0xffffffffu, v, o);
    return v;
}

// ======================= kernel 0: fp16 weight convert =======================
extern "C" __global__ void wsplit10_kernel(
    const float* __restrict__ a0, const float* __restrict__ a1,
    const float* __restrict__ a2, const float* __restrict__ a3,
    const float* __restrict__ a4, const float* __restrict__ a5,
    const float* __restrict__ a6, const float* __restrict__ a7,
    const float* __restrict__ a8, const float* __restrict__ a9) {
    const float* srcs[10] = {a0, a1, a2, a3, a4, a5, a6, a7, a8, a9};
    const float* src = srcs[blockIdx.y];
    int idx = blockIdx.x * 256 + threadIdx.x;
    g_wh[(size_t)blockIdx.y * WSZ + idx] = __float2half_rn(src[idx]);
}

// ======================= x-GEMM (fp16 2-split, 128x128 tiles) ================
// A = x [1024x512], B = 4 concatenated fp16 weights (N=2048); output routed.
constexpr int KC  = 32;
constexpr int AST = 40;   // smem row stride (fp16)

extern "C" __global__ void __launch_bounds__(256, 2)
x_gemm_kernel(const float* __restrict__ A, const __half* __restrict__ Bh) {
    __shared__ __half s_ahi[128 * AST];
    __shared__ __half s_alo[128 * AST];
    __shared__ __half s_b  [128 * AST];

    int tid = threadIdx.x, lane = tid & 31, wid = tid >> 5;
    int rowBase = blockIdx.x * 128;
    int colBase = blockIdx.y * 128;
    int wm = wid & 3, wn = wid >> 2;

    uint32_t ua_hi = smem_u32(s_ahi), ua_lo = smem_u32(s_alo);
    uint32_t ub    = smem_u32(s_b);

    float acc[2][8][4];
#pragma unroll
    for (int mt = 0; mt < 2; mt++)
#pragma unroll
        for (int nt = 0; nt < 8; nt++)
#pragma unroll
            for (int q = 0; q < 4; q++) acc[mt][nt][q] = 0.f;

    int rr = tid >> 1, half = tid & 1;
    const float*  aptr = A  + (size_t)(rowBase + rr) * CD + half * 16;
    const __half* bptr = Bh + (size_t)(colBase + rr) * CD + half * 16;
    uint32_t soff = (uint32_t)(rr * AST + half * 16) * 2;

    for (int k0 = 0; k0 < CD; k0 += KC) {
        __syncthreads();
#pragma unroll
        for (int q = 0; q < 4; q++) {
            float4 v = *(const float4*)(aptr + k0 + q * 4);
            __half hx = __float2half_rn(v.x), hy = __float2half_rn(v.y);
            __half hz = __float2half_rn(v.z), hw = __float2half_rn(v.w);
            sts64(ua_hi + soff + q * 8, pack_h2(hx, hy), pack_h2(hz, hw));
            sts64(ua_lo + soff + q * 8,
                  pack_h2(__float2half_rn(v.x - __half2float(hx)),
                          __float2half_rn(v.y - __half2float(hy))),
                  pack_h2(__float2half_rn(v.z - __half2float(hz)),
                          __float2half_rn(v.w - __half2float(hw))));
        }
#pragma unroll
        for (int q = 0; q < 2; q++)
            sts128(ub + soff + q * 16, *(const uint4*)(bptr + k0 + q * 8));
        __syncthreads();

#pragma unroll
        for (int kk = 0; kk < 2; kk++) {
            uint32_t b[8][2];
#pragma unroll
            for (int np = 0; np < 4; np++) {
                int n   = wn * 64 + np * 16 + (lane & 7) + ((lane >> 4) << 3);
                int kel = kk * 16 + (((lane >> 3) & 1) << 3);
                uint32_t r0, r1, r2, r3;
                ldm_x4(ub + (uint32_t)(n * AST + kel) * 2, r0, r1, r2, r3);
                b[np * 2][0] = r0; b[np * 2][1] = r1;
                b[np * 2 + 1][0] = r2; b[np * 2 + 1][1] = r3;
            }
#pragma unroll
            for (int seg = 0; seg < 2; seg++) {
                uint32_t sa = seg ? ua_lo : ua_hi;
                uint32_t a[2][4];
#pragma unroll
                for (int mt = 0; mt < 2; mt++) {
                    int row = wm * 32 + mt * 16 + (lane & 15);
                    int kel = kk * 16 + ((lane >> 4) << 3);
                    ldm_x4(sa + (uint32_t)(row * AST + kel) * 2,
                           a[mt][0], a[mt][1], a[mt][2], a[mt][3]);
                }
#pragma unroll
                for (int mt = 0; mt < 2; mt++)
#pragma unroll
                    for (int nt = 0; nt < 8; nt++)
                        mma_f16(acc[mt][nt], a[mt][0], a[mt][1], a[mt][2], a[mt][3],
                                b[nt][0], b[nt][1]);
            }
        }
    }

    int r0 = wm * 32 + (lane >> 2);
    int c0 = wn * 64 + (lane & 3) * 2;
    const int mat = colBase >> 9;
    float* O = (mat == 0) ? g_Vix : (mat == 1) ? g_Vjx : (mat == 2) ? g_Ujx : g_xWU;
    int cb = colBase & 511;
#pragma unroll
    for (int mt = 0; mt < 2; mt++) {
        int gr = rowBase + r0 + mt * 16;
#pragma unroll
        for (int nt = 0; nt < 8; nt++) {
            int c = cb + c0 + nt * 8;
            *(float2*)&O[(size_t)gr * CD + c] = make_float2(acc[mt][nt][0], acc[mt][nt][1]);
            *(float2*)&O[(size_t)(gr + 8) * CD + c] = make_float2(acc[mt][nt][2], acc[mt][nt][3]);
        }
    }
}

// ======================= fused edge GEMM + LN + residual =====================
// CTA: 32 edge rows x full N=512. eout = ein + relu(LN(ein@WE.T + Vix + Vjx))
// 8 warps: wm = wid&1 (16-row half), wn = wid>>1 (128-col quarter).
// B double-buffered via cp.async; A split fp16 hi/lo on the fly.
constexpr int BST     = 40;                       // B/A smem row stride (fp16)
constexpr int SB_SZ   = 512 * BST * 2;            // 40960 B per stage
constexpr int SM_SB0  = 0;
constexpr int SM_SB1  = SB_SZ;
constexpr int SM_AH   = 2 * SB_SZ;                // 81920
constexpr int SM_AL   = SM_AH + 32 * BST * 2;     // +2560
constexpr int SM_RED  = SM_AL + 32 * BST * 2;     // +2560
constexpr int SMEM_EDGE = SM_RED + 32 * 4 * 8;    // + s_red float2[32][4] = 88064

extern "C" __global__ void __launch_bounds__(256, 2)
edge_fused_kernel(const float* __restrict__ Ein, const __half* __restrict__ Wh,
                  const float* __restrict__ ge, const float* __restrict__ be,
                  float* __restrict__ Eout) {
    extern __shared__ char smc[];
    uint32_t sb = smem_u32(smc);
    int tid = threadIdx.x, lane = tid & 31, wid = tid >> 5;
    int wm = wid & 1, wn = wid >> 1;
    int rowBase = blockIdx.x * 32;

    float acc[16][4];
#pragma unroll
    for (int nt = 0; nt < 16; nt++)
#pragma unroll
        for (int q = 0; q < 4; q++) acc[nt][q] = 0.f;

    // B loader lambda-ish: each thread 8x cp.async16 per chunk
    int bu_n = tid >> 2, bu_k = tid & 3;   // base: covers n = bu_n + 64*q
    // A split assignment: one float4 per thread of the 32x32 chunk
    int arow = tid >> 3, acol = (tid & 7) * 4;
    const float* aptr = Ein + (size_t)(rowBase + arow) * CD + acol;

    // prologue: issue B chunk 0
#pragma unroll
    for (int q = 0; q < 8; q++) {
        int n = bu_n + q * 64;
        cp_async16(sb + SM_SB0 + (uint32_t)(n * BST + bu_k * 8) * 2,
                   Wh + (size_t)n * CD + bu_k * 8);
    }
    CP_COMMIT();
    float4 av = *(const float4*)(aptr);

    for (int ch = 0; ch < 16; ch++) {
        __syncthreads();                       // prev MMA done: s_a + next B stage free
        if (ch < 15) {
            uint32_t dst = sb + ((ch + 1) & 1 ? SM_SB1 : SM_SB0);
            const __half* src = Wh + (ch + 1) * 32;
#pragma unroll
            for (int q = 0; q < 8; q++) {
                int n = bu_n + q * 64;
                cp_async16(dst + (uint32_t)(n * BST + bu_k * 8) * 2,
                           src + (size_t)n * CD + bu_k * 8);
            }
            CP_COMMIT();
        }
        // convert current A chunk
        {
            __half hx = __float2half_rn(av.x), hy = __float2half_rn(av.y);
            __half hz = __float2half_rn(av.z), hw = __float2half_rn(av.w);
            uint32_t ao = (uint32_t)(arow * BST + acol) * 2;
            sts64(sb + SM_AH + ao, pack_h2(hx, hy), pack_h2(hz, hw));
            sts64(sb + SM_AL + ao,
                  pack_h2(__float2half_rn(av.x - __half2float(hx)),
                          __float2half_rn(av.y - __half2float(hy))),
                  pack_h2(__float2half_rn(av.z - __half2float(hz)),
                          __float2half_rn(av.w - __half2float(hw))));
        }
        if (ch < 15) av = *(const float4*)(aptr + (ch + 1) * 32);
        if (ch < 15) { CP_WAIT_1(); } else { CP_WAIT_0(); }
        __syncthreads();                       // A stores + B arrival visible

        uint32_t sbB = sb + ((ch & 1) ? SM_SB1 : SM_SB0);
#pragma unroll
        for (int kk = 0; kk < 2; kk++) {
            uint32_t b[8][4];
#pragma unroll
            for (int np = 0; np < 8; np++) {
                int n   = wn * 128 + np * 16 + (lane & 7) + ((lane >> 4) << 3);
                int kel = kk * 16 + (((lane >> 3) & 1) << 3);
                ldm_x4(sbB + (uint32_t)(n * BST + kel) * 2,
                       b[np][0], b[np][1], b[np][2], b[np][3]);
            }
            int row = wm * 16 + (lane & 15);
            int kel = kk * 16 + ((lane >> 4) << 3);
            uint32_t a0, a1, a2, a3;
            ldm_x4(sb + SM_AH + (uint32_t)(row * BST + kel) * 2, a0, a1, a2, a3);
#pragma unroll
            for (int np = 0; np < 8; np++) {
                mma_f16(acc[np * 2],     a0, a1, a2, a3, b[np][0], b[np][1]);
                mma_f16(acc[np * 2 + 1], a0, a1, a2, a3, b[np][2], b[np][3]);
            }
            ldm_x4(sb + SM_AL + (uint32_t)(row * BST + kel) * 2, a0, a1, a2, a3);
#pragma unroll
            for (int np = 0; np < 8; np++) {
                mma_f16(acc[np * 2],     a0, a1, a2, a3, b[np][0], b[np][1]);
                mma_f16(acc[np * 2 + 1], a0, a1, a2, a3, b[np][2], b[np][3]);
            }
        }
    }

    // ---- fused epilogue: m = acc + Vix + Vjx; LN; out = ein + relu(.) ----
    float2* s_red = (float2*)(smc + SM_RED);   // [row 0..31][wn 0..3] (sum, ss)
    int r0 = wm * 16 + (lane >> 2);
    int c0 = wn * 128 + (lane & 3) * 2;
    int bI = rowBase >> 12, iI = (rowBase >> 6) & 63;
    const float* vix = g_Vix + (size_t)((bI << 6) + iI) * CD;

#pragma unroll
    for (int h = 0; h < 2; h++) {
        int rloc = r0 + h * 8;
        int grow = rowBase + rloc;
        const float* vjx = g_Vjx + (size_t)((bI << 6) + (grow & 63)) * CD;
        float sum = 0.f, ss = 0.f;
#pragma unroll
        for (int nt = 0; nt < 16; nt++) {
            int c = c0 + nt * 8;
            float2 vi = *(const float2*)&vix[c];
            float2 vj = *(const float2*)&vjx[c];
            float m0 = acc[nt][h * 2 + 0] + vi.x + vj.x;
            float m1 = acc[nt][h * 2 + 1] + vi.y + vj.y;
            acc[nt][h * 2 + 0] = m0;
            acc[nt][h * 2 + 1] = m1;
            sum += m0 + m1;
            ss  += m0 * m0 + m1 * m1;
        }
        sum += __shfl_xor_sync(0xffffffffu, sum, 1);
        sum += __shfl_xor_sync(0xffffffffu, sum, 2);
        ss  += __shfl_xor_sync(0xffffffffu, ss, 1);
        ss  += __shfl_xor_sync(0xffffffffu, ss, 2);
        if ((lane & 3) == 0) s_red[rloc * 4 + wn] = make_float2(sum, ss);
    }
    __syncthreads();

#pragma unroll
    for (int h = 0; h < 2; h++) {
        int rloc = r0 + h * 8;
        int grow = rowBase + rloc;
        float2 p0 = s_red[rloc * 4 + 0], p1 = s_red[rloc * 4 + 1];
        float2 p2 = s_red[rloc * 4 + 2], p3 = s_red[rloc * 4 + 3];
        float sum = p0.x + p1.x + p2.x + p3.x;
        float ss  = p0.y + p1.y + p2.y + p3.y;
        float mean = sum * (1.f / CD);
        float var  = ss * (1.f / CD) - mean * mean;
        float inv  = rsqrtf(var + 1e-5f);
        const float* ein = Ein  + (size_t)grow * CD;
        float*       eo  = Eout + (size_t)grow * CD;
#pragma unroll
        for (int nt = 0; nt < 16; nt++) {
            int c = c0 + nt * 8;
            float2 g  = *(const float2*)&ge[c];
            float2 bb = *(const float2*)&be[c];
            float2 e  = *(const float2*)&ein[c];
            float2 o;
            o.x = e.x + fmaxf((acc[nt][h * 2 + 0] - mean) * inv * g.x + bb.x, 0.f);
            o.y = e.y + fmaxf((acc[nt][h * 2 + 1] - mean) * inv * g.y + bb.y, 0.f);
            *(float2*)&eo[c] = o;
        }
    }
}

// ======================= softmax-over-j + weighted agg =======================
extern "C" __global__ void softmax_agg_kernel(const float* __restrict__ E) {
    int bi = blockIdx.x;
    int b  = bi >> 6;
    int c  = threadIdx.x;
    const float* ep = E     + (size_t)bi * NN * CD + c;
    const float* up = g_Ujx + (size_t)b  * NN * CD + c;
    float se = 0.f, sw = 0.f;
#pragma unroll 4
    for (int j = 0; j < NN; j++) {
        float v  = ep[(size_t)j * CD];
        float sg = 1.f / (1.f + __expf(-v));
        float e  = __expf(sg);
        se += e;
        sw = fmaf(e, up[(size_t)j * CD], sw);
    }
    g_agg[(size_t)bi * CD + c] = sw / (se * (float)NN);
}

// ======================= x update ===========================================
extern "C" __global__ void x_update_kernel(const float* __restrict__ xres,
                                           const float* __restrict__ gv,
                                           const float* __restrict__ bv,
                                           float* __restrict__ xout) {
    int warp = threadIdx.x >> 5, lane = threadIdx.x & 31;
    int row  = blockIdx.x * 8 + warp;
    const float* a  = g_xWU + (size_t)row * CD;
    const float* ag = g_agg + (size_t)row * CD;
    float t[16];
    float s = 0.f;
#pragma unroll
    for (int v = 0; v < 16; v++) {
        int c = lane + 32 * v;
        t[v]  = a[c] + ag[c];
        s += t[v];
    }
    s = warp_sum(s);
    float mean = s * (1.f / CD);
    float q = 0.f;
#pragma unroll
    for (int v = 0; v < 16; v++) { float d = t[v] - mean; q += d * d; }
    q = warp_sum(q);
    float inv = rsqrtf(q * (1.f / CD) + 1e-5f);
    const float* r = xres + (size_t)row * CD;
    float*       o = xout + (size_t)row * CD;
#pragma unroll
    for (int v = 0; v < 16; v++) {
        int c = lane + 32 * v;
        float val = (t[v] - mean) * inv * gv[c] + bv[c];
        o[c] = fmaxf(r[c] + val, 0.f);
    }
}

// ===========================================================================
extern "C" void kernel_launch(void* const* d_in, const int* in_sizes, int n_in,
                              void* d_out, int out_size) {
    const float* x    = (const float*)d_in[0];
    const float* edge = (const float*)d_in[1];
    const float* WA1  = (const float*)d_in[2];
    const float* WB1  = (const float*)d_in[3];
    const float* WE1  = (const float*)d_in[4];
    const float* WU1  = (const float*)d_in[5];
    const float* WV1  = (const float*)d_in[6];
    const float* WA2  = (const float*)d_in[7];
    const float* WB2  = (const float*)d_in[8];
    const float* WE2  = (const float*)d_in[9];
    const float* WU2  = (const float*)d_in[10];
    const float* WV2  = (const float*)d_in[11];
    const float* ge1  = (const float*)d_in[12];
    const float* gv1  = (const float*)d_in[13];
    const float* ge2  = (const float*)d_in[14];
    const float* gv2  = (const float*)d_in[15];
    const float* be1  = (const float*)d_in[16];
    const float* bv1  = (const float*)d_in[17];
    const float* be2  = (const float*)d_in[18];
    const float* bv2  = (const float*)d_in[19];

    float* xout = (float*)d_out;
    float* eout = (float*)d_out + XEL;

    void* p = nullptr;
    cudaGetSymbolAddress(&p, g_x1); float* x1 = (float*)p;
    cudaGetSymbolAddress(&p, g_wh); __half* wh = (__half*)p;

    cudaFuncSetAttribute(edge_fused_kernel,
                         cudaFuncAttributeMaxDynamicSharedMemorySize, SMEM_EDGE);

    wsplit10_kernel<<<dim3(WSZ / 256, 10), 256>>>(WE1, WE2,
        WA1, WB1, WV1, WU1, WA2, WB2, WV2, WU2);

    // ---- layer 1 ----
    x_gemm_kernel<<<dim3(XROWS / 128, 16), 256>>>(x, wh + 2 * (size_t)WSZ);
    edge_fused_kernel<<<EROWS / 32, 256, SMEM_EDGE>>>(edge, wh, ge1, be1, eout);
    softmax_agg_kernel<<<XROWS, 512>>>(eout);
    x_update_kernel<<<XROWS / 8, 256>>>(x, gv1, bv1, x1);

    // ---- layer 2 (edge path in place on eout) ----
    x_gemm_kernel<<<dim3(XROWS / 128, 16), 256>>>(x1, wh + 6 * (size_t)WSZ);
    edge_fused_kernel<<<EROWS / 32, 256, SMEM_EDGE>>>(eout, wh + (size_t)WSZ, ge2, be2, eout);
    softmax_agg_kernel<<<XROWS, 512>>>(eout);
    x_update_kernel<<<XROWS / 8, 256>>>(x1, gv2, bv2, xout);
}

// round 10
// speedup vs baseline: 4.1169x; 1.1894x over previous
#include <cuda_runtime.h>
#include <cuda_fp16.h>
#include <cstdint>

// Problem dims
constexpr int CD    = 512;
constexpr int NB    = 16;
constexpr int NN    = 64;
constexpr int XROWS = NB * NN;        // 1024
constexpr int XEL   = XROWS * CD;     // 524288
constexpr int EROWS = NB * NN * NN;   // 65536
constexpr int WSZ   = CD * CD;        // 262144

// Scratch
__device__ float g_Vix[XEL];
__device__ float g_Vjx[XEL];
__device__ float g_Ujx[XEL];
__device__ float g_xWU[XEL];
__device__ float g_x1 [XEL];
// fp16 weights: [0]=WE1 [1]=WE2 [2..5]=WA1,WB1,WV1,WU1 [6..9]=WA2,WB2,WV2,WU2
__device__ __half g_wh[10 * WSZ];

// ======================= helpers =======================
__device__ __forceinline__ uint32_t smem_u32(const void* p) {
    uint32_t a;
    asm("{ .reg .u64 t; cvta.to.shared.u64 t, %1; cvt.u32.u64 %0, t; }" : "=r"(a) : "l"(p));
    return a;
}
__device__ __forceinline__ void ldm_x4(uint32_t addr, uint32_t& r0, uint32_t& r1,
                                       uint32_t& r2, uint32_t& r3) {
    asm volatile("ldmatrix.sync.aligned.m8n8.x4.shared.b16 {%0,%1,%2,%3}, [%4];"
                 : "=r"(r0), "=r"(r1), "=r"(r2), "=r"(r3) : "r"(addr));
}
__device__ __forceinline__ void mma_f16(float* c, uint32_t a0, uint32_t a1, uint32_t a2,
                                        uint32_t a3, uint32_t b0, uint32_t b1) {
    asm volatile(
        "mma.sync.aligned.m16n8k16.row.col.f32.f16.f16.f32 "
        "{%0,%1,%2,%3}, {%4,%5,%6,%7}, {%8,%9}, {%0,%1,%2,%3};"
        : "+f"(c[0]), "+f"(c[1]), "+f"(c[2]), "+f"(c[3])
        : "r"(a0), "r"(a1), "r"(a2), "r"(a3), "r"(b0), "r"(b1));
}
__device__ __forceinline__ void sts64(uint32_t addr, uint32_t w0, uint32_t w1) {
    asm volatile("st.shared.v2.b32 [%0], {%1, %2};" :: "r"(addr), "r"(w0), "r"(w1) : "memory");
}
__device__ __forceinline__ void sts128(uint32_t addr, uint4 v) {
    asm volatile("st.shared.v4.b32 [%0], {%1, %2, %3, %4};"
                 :: "r"(addr), "r"(v.x), "r"(v.y), "r"(v.z), "r"(v.w) : "memory");
}
__device__ __forceinline__ void cp_async16(uint32_t smem, const void* g) {
    asm volatile("cp.async.cg.shared.global [%0], [%1], 16;" :: "r"(smem), "l"(g) : "memory");
}
#define CP_COMMIT()  asm volatile("cp.async.commit_group;" ::: "memory")
#define CP_WAIT_0()  asm volatile("cp.async.wait_group 0;" ::: "memory")

__device__ __forceinline__ uint32_t pack_h2(__half a, __half b) {
    __half2 t = __halves2half2(a, b);
    return *reinterpret_cast<uint32_t*>(&t);
}
__device__ __forceinline__ float warp_sum(float v) {
#pragma unroll
    for (int o = 16; o > 0; o >>= 1) v += __shfl_xor_sync(0xffffffffu, v, o);
    return v;
}

// ======================= kernel 0: fp16 weight convert =======================
extern "C" __global__ void wsplit10_kernel(
    const float* __restrict__ a0, const float* __restrict__ a1,
    const float* __restrict__ a2, const float* __restrict__ a3,
    const float* __restrict__ a4, const float* __restrict__ a5,
    const float* __restrict__ a6, const float* __restrict__ a7,
    const float* __restrict__ a8, const float* __restrict__ a9) {
    const float* srcs[10] = {a0, a1, a2, a3, a4, a5, a6, a7, a8, a9};
    const float* src = srcs[blockIdx.y];
    int idx = blockIdx.x * 256 + threadIdx.x;
    g_wh[(size_t)blockIdx.y * WSZ + idx] = __float2half_rn(src[idx]);
}

// ======================= x-GEMM (fp16 2-split, 128x128 tiles) ================
constexpr int AST = 40;   // smem row stride (fp16)

extern "C" __global__ void __launch_bounds__(256, 2)
x_gemm_kernel(const float* __restrict__ A, const __half* __restrict__ Bh) {
    __shared__ __half s_ahi[128 * AST];
    __shared__ __half s_alo[128 * AST];
    __shared__ __half s_b  [128 * AST];

    int tid = threadIdx.x, lane = tid & 31, wid = tid >> 5;
    int rowBase = blockIdx.x * 128;
    int colBase = blockIdx.y * 128;
    int wm = wid & 3, wn = wid >> 2;

    uint32_t ua_hi = smem_u32(s_ahi), ua_lo = smem_u32(s_alo);
    uint32_t ub    = smem_u32(s_b);

    float acc[2][8][4];
#pragma unroll
    for (int mt = 0; mt < 2; mt++)
#pragma unroll
        for (int nt = 0; nt < 8; nt++)
#pragma unroll
            for (int q = 0; q < 4; q++) acc[mt][nt][q] = 0.f;

    int rr = tid >> 1, half = tid & 1;
    const float*  aptr = A  + (size_t)(rowBase + rr) * CD + half * 16;
    const __half* bptr = Bh + (size_t)(colBase + rr) * CD + half * 16;
    uint32_t soff = (uint32_t)(rr * AST + half * 16) * 2;

    for (int k0 = 0; k0 < CD; k0 += 32) {
        __syncthreads();
#pragma unroll
        for (int q = 0; q < 4; q++) {
            float4 v = *(const float4*)(aptr + k0 + q * 4);
            __half hx = __float2half_rn(v.x), hy = __float2half_rn(v.y);
            __half hz = __float2half_rn(v.z), hw = __float2half_rn(v.w);
            sts64(ua_hi + soff + q * 8, pack_h2(hx, hy), pack_h2(hz, hw));
            sts64(ua_lo + soff + q * 8,
                  pack_h2(__float2half_rn(v.x - __half2float(hx)),
                          __float2half_rn(v.y - __half2float(hy))),
                  pack_h2(__float2half_rn(v.z - __half2float(hz)),
                          __float2half_rn(v.w - __half2float(hw))));
        }
#pragma unroll
        for (int q = 0; q < 2; q++)
            sts128(ub + soff + q * 16, *(const uint4*)(bptr + k0 + q * 8));
        __syncthreads();

#pragma unroll
        for (int kk = 0; kk < 2; kk++) {
            uint32_t b[8][2];
#pragma unroll
            for (int np = 0; np < 4; np++) {
                int n   = wn * 64 + np * 16 + (lane & 7) + ((lane >> 4) << 3);
                int kel = kk * 16 + (((lane >> 3) & 1) << 3);
                uint32_t r0, r1, r2, r3;
                ldm_x4(ub + (uint32_t)(n * AST + kel) * 2, r0, r1, r2, r3);
                b[np * 2][0] = r0; b[np * 2][1] = r1;
                b[np * 2 + 1][0] = r2; b[np * 2 + 1][1] = r3;
            }
#pragma unroll
            for (int seg = 0; seg < 2; seg++) {
                uint32_t sa = seg ? ua_lo : ua_hi;
                uint32_t a[2][4];
#pragma unroll
                for (int mt = 0; mt < 2; mt++) {
                    int row = wm * 32 + mt * 16 + (lane & 15);
                    int kel = kk * 16 + ((lane >> 4) << 3);
                    ldm_x4(sa + (uint32_t)(row * AST + kel) * 2,
                           a[mt][0], a[mt][1], a[mt][2], a[mt][3]);
                }
#pragma unroll
                for (int mt = 0; mt < 2; mt++)
#pragma unroll
                    for (int nt = 0; nt < 8; nt++)
                        mma_f16(acc[mt][nt], a[mt][0], a[mt][1], a[mt][2], a[mt][3],
                                b[nt][0], b[nt][1]);
            }
        }
    }

    int r0 = wm * 32 + (lane >> 2);
    int c0 = wn * 64 + (lane & 3) * 2;
    const int mat = colBase >> 9;
    float* O = (mat == 0) ? g_Vix : (mat == 1) ? g_Vjx : (mat == 2) ? g_Ujx : g_xWU;
    int cb = colBase & 511;
#pragma unroll
    for (int mt = 0; mt < 2; mt++) {
        int gr = rowBase + r0 + mt * 16;
#pragma unroll
        for (int nt = 0; nt < 8; nt++) {
            int c = cb + c0 + nt * 8;
            *(float2*)&O[(size_t)gr * CD + c] = make_float2(acc[mt][nt][0], acc[mt][nt][1]);
            *(float2*)&O[(size_t)(gr + 8) * CD + c] = make_float2(acc[mt][nt][2], acc[mt][nt][3]);
        }
    }
}

// ======================= fused edge GEMM + LN + residual =====================
// CTA: 32 rows x 512 cols. 8 warps, warp tile 32 rows x 64 cols (wn = wid).
// One __syncthreads per K-chunk; A (hi/lo) double-buffered; B cp.async 2-stage.
constexpr int BST     = 40;                        // smem row stride (fp16)
constexpr int SB_SZ   = 512 * BST * 2;             // 40960 B per B stage
constexpr int SM_SB0  = 0;
constexpr int SM_SB1  = SB_SZ;                     // 40960
constexpr int SM_A    = 2 * SB_SZ;                 // 81920; 4 bufs of 2560
constexpr int A_SZ    = 32 * BST * 2;              // 2560
constexpr int SM_RED  = SM_A + 4 * A_SZ;           // 92160
constexpr int SMEM_EDGE = SM_RED + 32 * 8 * 8;     // + float2[32][8] = 94208

extern "C" __global__ void __launch_bounds__(256, 2)
edge_fused_kernel(const float* __restrict__ Ein, const __half* __restrict__ Wh,
                  const float* __restrict__ ge, const float* __restrict__ be,
                  float* __restrict__ Eout) {
    extern __shared__ char smc[];
    uint32_t sb = smem_u32(smc);
    int tid = threadIdx.x, lane = tid & 31, wn = tid >> 5;
    int rowBase = blockIdx.x * 32;

    float acc[2][8][4];
#pragma unroll
    for (int mt = 0; mt < 2; mt++)
#pragma unroll
        for (int nt = 0; nt < 8; nt++)
#pragma unroll
            for (int q = 0; q < 4; q++) acc[mt][nt][q] = 0.f;

    int bu_n = tid >> 2, bu_k = tid & 3;         // B: n = bu_n + 64q, 16B at bu_k*8 fp16
    int arow = tid >> 3, acol = (tid & 7) * 4;   // A: one float4 of the 32x32 chunk
    const float* aptr = Ein + (size_t)(rowBase + arow) * CD + acol;
    uint32_t aoff = (uint32_t)(arow * BST + acol) * 2;

    // prologue: B chunk 0 + A chunk 0
#pragma unroll
    for (int q = 0; q < 8; q++) {
        int n = bu_n + q * 64;
        cp_async16(sb + SM_SB0 + (uint32_t)(n * BST + bu_k * 8) * 2,
                   Wh + (size_t)n * CD + bu_k * 8);
    }
    CP_COMMIT();
    float4 av = *(const float4*)(aptr);
    {
        __half hx = __float2half_rn(av.x), hy = __float2half_rn(av.y);
        __half hz = __float2half_rn(av.z), hw = __float2half_rn(av.w);
        sts64(sb + SM_A + aoff, pack_h2(hx, hy), pack_h2(hz, hw));
        sts64(sb + SM_A + A_SZ + aoff,
              pack_h2(__float2half_rn(av.x - __half2float(hx)),
                      __float2half_rn(av.y - __half2float(hy))),
              pack_h2(__float2half_rn(av.z - __half2float(hz)),
                      __float2half_rn(av.w - __half2float(hw))));
    }
    av = *(const float4*)(aptr + 32);
    CP_WAIT_0();
    __syncthreads();

    for (int ch = 0; ch < 16; ch++) {
        int cur = ch & 1, nxt = cur ^ 1;
        // issue B(ch+1) into the stage freed by MMA(ch-1)
        if (ch < 15) {
            uint32_t dst = sb + (nxt ? SM_SB1 : SM_SB0);
            const __half* src = Wh + (size_t)(ch + 1) * 32;
#pragma unroll
            for (int q = 0; q < 8; q++) {
                int n = bu_n + q * 64;
                cp_async16(dst + (uint32_t)(n * BST + bu_k * 8) * 2,
                           src + (size_t)n * CD + bu_k * 8);
            }
            CP_COMMIT();
            // store A(ch+1) into A buf nxt
            __half hx = __float2half_rn(av.x), hy = __float2half_rn(av.y);
            __half hz = __float2half_rn(av.z), hw = __float2half_rn(av.w);
            uint32_t ab = sb + SM_A + (uint32_t)nxt * 2 * A_SZ;
            sts64(ab + aoff, pack_h2(hx, hy), pack_h2(hz, hw));
            sts64(ab + A_SZ + aoff,
                  pack_h2(__float2half_rn(av.x - __half2float(hx)),
                          __float2half_rn(av.y - __half2float(hy))),
                  pack_h2(__float2half_rn(av.z - __half2float(hz)),
                          __float2half_rn(av.w - __half2float(hw))));
            if (ch < 14) av = *(const float4*)(aptr + (ch + 2) * 32);
        }

        uint32_t sbB = sb + (cur ? SM_SB1 : SM_SB0);
        uint32_t sAh = sb + SM_A + (uint32_t)cur * 2 * A_SZ;
        uint32_t sAl = sAh + A_SZ;
#pragma unroll
        for (int kk = 0; kk < 2; kk++) {
            uint32_t b[4][4];
#pragma unroll
            for (int np = 0; np < 4; np++) {
                int n   = wn * 64 + np * 16 + (lane & 7) + ((lane >> 4) << 3);
                int kel = kk * 16 + (((lane >> 3) & 1) << 3);
                ldm_x4(sbB + (uint32_t)(n * BST + kel) * 2,
                       b[np][0], b[np][1], b[np][2], b[np][3]);
            }
            uint32_t a[2][4];
            int kel = kk * 16 + ((lane >> 4) << 3);
#pragma unroll
            for (int mt = 0; mt < 2; mt++) {
                int row = mt * 16 + (lane & 15);
                ldm_x4(sAh + (uint32_t)(row * BST + kel) * 2,
                       a[mt][0], a[mt][1], a[mt][2], a[mt][3]);
            }
#pragma unroll
            for (int mt = 0; mt < 2; mt++)
#pragma unroll
                for (int np = 0; np < 4; np++) {
                    mma_f16(acc[mt][np * 2],     a[mt][0], a[mt][1], a[mt][2], a[mt][3],
                            b[np][0], b[np][1]);
                    mma_f16(acc[mt][np * 2 + 1], a[mt][0], a[mt][1], a[mt][2], a[mt][3],
                            b[np][2], b[np][3]);
                }
#pragma unroll
            for (int mt = 0; mt < 2; mt++) {
                int row = mt * 16 + (lane & 15);
                ldm_x4(sAl + (uint32_t)(row * BST + kel) * 2,
                       a[mt][0], a[mt][1], a[mt][2], a[mt][3]);
            }
#pragma unroll
            for (int mt = 0; mt < 2; mt++)
#pragma unroll
                for (int np = 0; np < 4; np++) {
                    mma_f16(acc[mt][np * 2],     a[mt][0], a[mt][1], a[mt][2], a[mt][3],
                            b[np][0], b[np][1]);
                    mma_f16(acc[mt][np * 2 + 1], a[mt][0], a[mt][1], a[mt][2], a[mt][3],
                            b[np][2], b[np][3]);
                }
        }
        CP_WAIT_0();
        __syncthreads();
    }

    // ---- fused epilogue ----
    float2* s_red = (float2*)(smc + SM_RED);     // [row][wn]
    int r0 = lane >> 2;
    int c0 = wn * 64 + (lane & 3) * 2;
    int bI = rowBase >> 12, iI = (rowBase >> 6) & 63;
    const float* vix = g_Vix + (size_t)((bI << 6) + iI) * CD;

#pragma unroll
    for (int mt = 0; mt < 2; mt++)
#pragma unroll
        for (int h = 0; h < 2; h++) {
            int rloc = mt * 16 + h * 8 + r0;
            int grow = rowBase + rloc;
            const float* vjx = g_Vjx + (size_t)((bI << 6) + (grow & 63)) * CD;
            float sum = 0.f, ss = 0.f;
#pragma unroll
            for (int nt = 0; nt < 8; nt++) {
                int c = c0 + nt * 8;
                float2 vi = *(const float2*)&vix[c];
                float2 vj = *(const float2*)&vjx[c];
                float m0 = acc[mt][nt][h * 2 + 0] + vi.x + vj.x;
                float m1 = acc[mt][nt][h * 2 + 1] + vi.y + vj.y;
                acc[mt][nt][h * 2 + 0] = m0;
                acc[mt][nt][h * 2 + 1] = m1;
                sum += m0 + m1;
                ss  += m0 * m0 + m1 * m1;
            }
            sum += __shfl_xor_sync(0xffffffffu, sum, 1);
            sum += __shfl_xor_sync(0xffffffffu, sum, 2);
            ss  += __shfl_xor_sync(0xffffffffu, ss, 1);
            ss  += __shfl_xor_sync(0xffffffffu, ss, 2);
            if ((lane & 3) == 0) s_red[rloc * 8 + wn] = make_float2(sum, ss);
        }
    __syncthreads();

#pragma unroll
    for (int mt = 0; mt < 2; mt++)
#pragma unroll
        for (int h = 0; h < 2; h++) {
            int rloc = mt * 16 + h * 8 + r0;
            int grow = rowBase + rloc;
            float sum = 0.f, ss = 0.f;
#pragma unroll
            for (int w = 0; w < 8; w++) {
                float2 pp = s_red[rloc * 8 + w];
                sum += pp.x; ss += pp.y;
            }
            float mean = sum * (1.f / CD);
            float var  = ss * (1.f / CD) - mean * mean;
            float inv  = rsqrtf(var + 1e-5f);
            const float* ein = Ein  + (size_t)grow * CD;
            float*       eo  = Eout + (size_t)grow * CD;
#pragma unroll
            for (int nt = 0; nt < 8; nt++) {
                int c = c0 + nt * 8;
                float2 g  = *(const float2*)&ge[c];
                float2 bb = *(const float2*)&be[c];
                float2 e  = *(const float2*)&ein[c];
                float2 o;
                o.x = e.x + fmaxf((acc[mt][nt][h * 2 + 0] - mean) * inv * g.x + bb.x, 0.f);
                o.y = e.y + fmaxf((acc[mt][nt][h * 2 + 1] - mean) * inv * g.y + bb.y, 0.f);
                *(float2*)&eo[c] = o;
            }
        }
}

// ============== fused softmax-over-j + agg + x LN update ====================
// block = (b,i) row pair; 256 threads, each owns channels c and c+256.
extern "C" __global__ void __launch_bounds__(256)
softmax_x_kernel(const float* __restrict__ E, const float* __restrict__ xres,
                 const float* __restrict__ gv, const float* __restrict__ bv,
                 float* __restrict__ xout) {
    __shared__ float s_sum[8], s_ss[8];
    int bi = blockIdx.x;
    int b  = bi >> 6;
    int c  = threadIdx.x;
    const float* ep = E     + (size_t)bi * NN * CD + c;
    const float* up = g_Ujx + (size_t)b  * NN * CD + c;
    float se0 = 0.f, sw0 = 0.f, se1 = 0.f, sw1 = 0.f;
#pragma unroll 4
    for (int j = 0; j < NN; j++) {
        float v0  = ep[(size_t)j * CD];
        float v1  = ep[(size_t)j * CD + 256];
        float sg0 = __frcp_rn(1.f + __expf(-v0));
        float sg1 = __frcp_rn(1.f + __expf(-v1));
        float e0  = __expf(sg0);
        float e1  = __expf(sg1);
        se0 += e0; se1 += e1;
        sw0 = fmaf(e0, up[(size_t)j * CD], sw0);
        sw1 = fmaf(e1, up[(size_t)j * CD + 256], sw1);
    }
    const float* a = g_xWU + (size_t)bi * CD;
    float t0 = a[c]       + sw0 / (se0 * (float)NN);
    float t1 = a[c + 256] + sw1 / (se1 * (float)NN);

    float sum = warp_sum(t0 + t1);
    float ss  = warp_sum(t0 * t0 + t1 * t1);
    int lane = c & 31, wid = c >> 5;
    if (lane == 0) { s_sum[wid] = sum; s_ss[wid] = ss; }
    __syncthreads();
    sum = 0.f; ss = 0.f;
#pragma unroll
    for (int w = 0; w < 8; w++) { sum += s_sum[w]; ss += s_ss[w]; }
    float mean = sum * (1.f / CD);
    float var  = ss * (1.f / CD) - mean * mean;
    float inv  = rsqrtf(var + 1e-5f);
    const float* r = xres + (size_t)bi * CD;
    float*       o = xout + (size_t)bi * CD;
    float v0 = (t0 - mean) * inv * gv[c]       + bv[c];
    float v1 = (t1 - mean) * inv * gv[c + 256] + bv[c + 256];
    o[c]       = fmaxf(r[c]       + v0, 0.f);
    o[c + 256] = fmaxf(r[c + 256] + v1, 0.f);
}

// ===========================================================================
extern "C" void kernel_launch(void* const* d_in, const int* in_sizes, int n_in,
                              void* d_out, int out_size) {
    const float* x    = (const float*)d_in[0];
    const float* edge = (const float*)d_in[1];
    const float* WA1  = (const float*)d_in[2];
    const float* WB1  = (const float*)d_in[3];
    const float* WE1  = (const float*)d_in[4];
    const float* WU1  = (const float*)d_in[5];
    const float* WV1  = (const float*)d_in[6];
    const float* WA2  = (const float*)d_in[7];
    const float* WB2  = (const float*)d_in[8];
    const float* WE2  = (const float*)d_in[9];
    const float* WU2  = (const float*)d_in[10];
    const float* WV2  = (const float*)d_in[11];
    const float* ge1  = (const float*)d_in[12];
    const float* gv1  = (const float*)d_in[13];
    const float* ge2  = (const float*)d_in[14];
    const float* gv2  = (const float*)d_in[15];
    const float* be1  = (const float*)d_in[16];
    const float* bv1  = (const float*)d_in[17];
    const float* be2  = (const float*)d_in[18];
    const float* bv2  = (const float*)d_in[19];

    float* xout = (float*)d_out;
    float* eout = (float*)d_out + XEL;

    void* p = nullptr;
    cudaGetSymbolAddress(&p, g_x1); float* x1 = (float*)p;
    cudaGetSymbolAddress(&p, g_wh); __half* wh = (__half*)p;

    cudaFuncSetAttribute(edge_fused_kernel,
                         cudaFuncAttributeMaxDynamicSharedMemorySize, SMEM_EDGE);

    wsplit10_kernel<<<dim3(WSZ / 256, 10), 256>>>(WE1, WE2,
        WA1, WB1, WV1, WU1, WA2, WB2, WV2, WU2);

    // ---- layer 1 ----
    x_gemm_kernel<<<dim3(XROWS / 128, 16), 256>>>(x, wh + 2 * (size_t)WSZ);
    edge_fused_kernel<<<EROWS / 32, 256, SMEM_EDGE>>>(edge, wh, ge1, be1, eout);
    softmax_x_kernel<<<XROWS, 256>>>(eout, x, gv1, bv1, x1);

    // ---- layer 2 (edge path in place on eout) ----
    x_gemm_kernel<<<dim3(XROWS / 128, 16), 256>>>(x1, wh + 6 * (size_t)WSZ);
    edge_fused_kernel<<<EROWS / 32, 256, SMEM_EDGE>>>(eout, wh + (size_t)WSZ, ge2, be2, eout);
    softmax_x_kernel<<<XROWS, 256>>>(eout, x1, gv2, bv2, xout);
}